// round 15
// baseline (speedup 1.0000x reference)
#include <cuda_runtime.h>
#include <cstdint>

#define L_LEN   65536
#define L_MASK  (L_LEN - 1)
#define CIN     8
#define COUT    8
#define FS      4
#define TPB     64         // 2 autonomous warps per block
#define WTILE   256        // positions per warp-tile
#define NT      4          // tiles per warp (warp covers 1024 positions)
#define ROWW    260        // 256 + 4 halo floats, 16B-aligned row stride

// ---- packed f32x2 helpers (Blackwell sm_100a+) ------------------------------
__device__ __forceinline__ float2 ffma2(float2 a, float2 b, float2 c) {
    float2 d;
    asm("fma.rn.f32x2 %0, %1, %2, %3;"
        : "=l"(reinterpret_cast<unsigned long long&>(d))
        : "l"(reinterpret_cast<const unsigned long long&>(a)),
          "l"(reinterpret_cast<const unsigned long long&>(b)),
          "l"(reinterpret_cast<const unsigned long long&>(c)));
    return d;
}

__device__ __forceinline__ float2 dup2(float x) {
    float2 d;
    asm("mov.b64 %0, {%1, %1};"
        : "=l"(reinterpret_cast<unsigned long long&>(d))
        : "f"(x));
    return d;
}

__device__ __forceinline__ uint32_t smem_u32(const void* p) {
    uint32_t a;
    asm("{ .reg .u64 t; cvta.to.shared.u64 t, %1; cvt.u32.u64 %0, t; }"
        : "=r"(a) : "l"(p));
    return a;
}

__device__ __forceinline__ void cp_async16(uint32_t dst, const float* src) {
    asm volatile("cp.async.cg.shared.global [%0], [%1], 16;"
                 :: "r"(dst), "l"(src));
}

// ----------------------------------------------------------------------------
// out[b, co, l] = bias[co] + sum_{ci,k} x[b, ci, (l+k) mod L] * W[co, ci, k]
//
// Warp-private double-buffered cp.async pipeline, ZERO block-level syncs.
// Each warp owns 1024 positions as 4 tiles of 256, a private 2-buffer SMEM
// region, and its own cp.async group stream (group state is per-thread;
// every lane waits on its own groups before __syncwarp, so after the warp
// sync the whole tile is resident). Tile i+2 is issued right after tile i's
// compute: a full compute phase of lead time hides DRAM latency
// deterministically; only tile 0 of 4 is exposed.
// R14 bug fixed: second-bundle SMEM offset is 512B (128 floats), not 2048B.
// Lane owns bundles at 4*lid and 128+4*lid within each tile: conflict-free
// LDS.128 windows, warp-coalesced STG.128. All 8 co as 4 f32x2 pairs.
// ----------------------------------------------------------------------------
__global__ __launch_bounds__(TPB, 6)
void conv_pbc_kernel(const float* __restrict__ x,
                     const float* __restrict__ W,
                     const float* __restrict__ bias,
                     float* __restrict__ out)
{
    __shared__ float xs[2][2][CIN][ROWW];                    // [warp][buf]
    __shared__ __align__(16) float2 w2s[2][CIN][FS][COUT/2]; // per-warp W
    __shared__ float2 b2s[2][COUT / 2];                      // per-warp bias

    const int t   = threadIdx.x;
    const int w   = t >> 5;
    const int lid = t & 31;

    const int b  = blockIdx.x >> 5;                 // 32 groups per batch
    const int wb = ((blockIdx.x & 31) << 11) + (w << 10);  // warp's 1024 pos

    const float* __restrict__ xb = x + (size_t)b * CIN * L_LEN;

    // ---- per-warp weights / bias (visible after first __syncwarp) ----
    {
        const int ci = (lid >> 2) & 7;
        const int k  = lid & 3;
        #pragma unroll
        for (int cp = 0; cp < 4; ++cp)
            w2s[w][ci][k][cp] =
                make_float2(W[(2 * cp)     * CIN * FS + ci * FS + k],
                            W[(2 * cp + 1) * CIN * FS + ci * FS + k]);
        if (lid < COUT / 2)
            b2s[w][lid] = make_float2(bias[2 * lid], bias[2 * lid + 1]);
    }

    const uint32_t xs_w = smem_u32(&xs[w][0][0][0]);

    // issue all cp.asyncs for warp-tile i into buffer buf (17 per thread max)
    auto issue_tile = [&](int i, int buf) {
        const int base = wb + (i << 8);
        const uint32_t dst0 = xs_w + (uint32_t)buf * (CIN * ROWW * 4);
        #pragma unroll
        for (int ci = 0; ci < CIN; ++ci) {
            const float* __restrict__ xc = xb + (size_t)ci * L_LEN + base;
            const uint32_t d = dst0 + ci * (ROWW * 4);
            cp_async16(d + 16u * lid,         xc + 4 * lid);
            cp_async16(d + 512u + 16u * lid,  xc + 128 + 4 * lid);
        }
        if (lid < CIN)   // halo: 4 floats past the tile, circular, aligned
            cp_async16(dst0 + lid * (ROWW * 4) + WTILE * 4,
                       xb + (size_t)lid * L_LEN + ((base + WTILE) & L_MASK));
    };

    // compute + store one resident warp-tile from buffer buf
    auto do_tile = [&](int i, int buf) {
        float2 acc[2][4][COUT / 2];
        {
            const float2 c0 = b2s[w][0], c1 = b2s[w][1],
                         c2 = b2s[w][2], c3 = b2s[w][3];
            #pragma unroll
            for (int j = 0; j < 2; ++j)
                #pragma unroll
                for (int q = 0; q < 4; ++q) {
                    acc[j][q][0] = c0; acc[j][q][1] = c1;
                    acc[j][q][2] = c2; acc[j][q][3] = c3;
                }
        }

        #pragma unroll
        for (int ci = 0; ci < CIN; ++ci) {
            float2 wv[FS][COUT / 2];
            #pragma unroll
            for (int k = 0; k < FS; ++k) {
                const float4 wa  = *reinterpret_cast<const float4*>(&w2s[w][ci][k][0]);
                const float4 wb4 = *reinterpret_cast<const float4*>(&w2s[w][ci][k][2]);
                wv[k][0] = make_float2(wa.x, wa.y);
                wv[k][1] = make_float2(wa.z, wa.w);
                wv[k][2] = make_float2(wb4.x, wb4.y);
                wv[k][3] = make_float2(wb4.z, wb4.w);
            }

            const float* __restrict__ row = &xs[w][buf][ci][0];
            float xw[2][8];
            {
                const float4 a0 = *reinterpret_cast<const float4*>(row + 4 * lid);
                const float4 a1 = *reinterpret_cast<const float4*>(row + 4 * lid + 4);
                const float4 b0 = *reinterpret_cast<const float4*>(row + 128 + 4 * lid);
                const float4 b1 = *reinterpret_cast<const float4*>(row + 128 + 4 * lid + 4);
                xw[0][0] = a0.x; xw[0][1] = a0.y; xw[0][2] = a0.z; xw[0][3] = a0.w;
                xw[0][4] = a1.x; xw[0][5] = a1.y; xw[0][6] = a1.z; xw[0][7] = a1.w;
                xw[1][0] = b0.x; xw[1][1] = b0.y; xw[1][2] = b0.z; xw[1][3] = b0.w;
                xw[1][4] = b1.x; xw[1][5] = b1.y; xw[1][6] = b1.z; xw[1][7] = b1.w;
            }

            #pragma unroll
            for (int j = 0; j < 2; ++j) {
                #pragma unroll
                for (int ii = 0; ii < 7; ++ii) {
                    const float2 xk = dup2(xw[j][ii]);
                    #pragma unroll
                    for (int k = 0; k < FS; ++k) {
                        const int q = ii - k;
                        if (q >= 0 && q < 4) {
                            #pragma unroll
                            for (int cp = 0; cp < 4; ++cp)
                                acc[j][q][cp] = ffma2(wv[k][cp], xk, acc[j][q][cp]);
                        }
                    }
                }
            }
        }

        // warp-coalesced STG.128 epilogue for this tile
        float* __restrict__ ob =
            out + (size_t)b * COUT * L_LEN + (wb + (i << 8)) + 4 * lid;
        #pragma unroll
        for (int cp = 0; cp < 4; ++cp) {
            #pragma unroll
            for (int j = 0; j < 2; ++j) {
                float4 v;
                v.x = acc[j][0][cp].x; v.y = acc[j][1][cp].x;
                v.z = acc[j][2][cp].x; v.w = acc[j][3][cp].x;
                *reinterpret_cast<float4*>(ob + (size_t)(2 * cp) * L_LEN + 128 * j) = v;
                v.x = acc[j][0][cp].y; v.y = acc[j][1][cp].y;
                v.z = acc[j][2][cp].y; v.w = acc[j][3][cp].y;
                *reinterpret_cast<float4*>(ob + (size_t)(2 * cp + 1) * L_LEN + 128 * j) = v;
            }
        }
    };

    // ---- per-warp pipeline: 2 tiles in flight, 1-tile lead during compute ----
    issue_tile(0, 0);
    asm volatile("cp.async.commit_group;");
    issue_tile(1, 1);
    asm volatile("cp.async.commit_group;");

    #pragma unroll
    for (int i = 0; i < NT; ++i) {
        asm volatile("cp.async.wait_group 1;");
        __syncwarp();                   // all lanes' cps for tile i complete

        do_tile(i, i & 1);

        __syncwarp();                   // all lanes done reading buf (i&1)
        if (i + 2 < NT)
            issue_tile(i + 2, i & 1);
        asm volatile("cp.async.commit_group;");   // empty group when no issue
    }
}

extern "C" void kernel_launch(void* const* d_in, const int* in_sizes, int n_in,
                              void* d_out, int out_size)
{
    const float* x    = (const float*)d_in[0];  // (64, 8, 65536)
    const float* W    = (const float*)d_in[1];  // (8, 8, 4)
    const float* bias = (const float*)d_in[2];  // (8,)
    float* out        = (float*)d_out;          // (64, 8, 65536)

    // 64 batches * 32 groups (2 warps * 1024 positions) = 2048 blocks of 64
    conv_pbc_kernel<<<64 * (L_LEN / 2048), TPB>>>(x, W, bias, out);
}

// round 16
// speedup vs baseline: 1.0674x; 1.0674x over previous
#include <cuda_runtime.h>
#include <cstdint>

#define L_LEN   65536
#define L_MASK  (L_LEN - 1)
#define CIN     8
#define COUT    8
#define FS      4
#define TPB     128        // 4 autonomous warps per block
#define WTILE   128        // positions per warp
#define ROWW    132        // 128 + 4 halo floats, 16B-aligned row stride

// ---- packed f32x2 helpers (Blackwell sm_100a+) ------------------------------
__device__ __forceinline__ float2 ffma2(float2 a, float2 b, float2 c) {
    float2 d;
    asm("fma.rn.f32x2 %0, %1, %2, %3;"
        : "=l"(reinterpret_cast<unsigned long long&>(d))
        : "l"(reinterpret_cast<const unsigned long long&>(a)),
          "l"(reinterpret_cast<const unsigned long long&>(b)),
          "l"(reinterpret_cast<const unsigned long long&>(c)));
    return d;
}

__device__ __forceinline__ float2 dup2(float x) {
    float2 d;
    asm("mov.b64 %0, {%1, %1};"
        : "=l"(reinterpret_cast<unsigned long long&>(d))
        : "f"(x));
    return d;
}

// ----------------------------------------------------------------------------
// out[b, co, l] = bias[co] + sum_{ci,k} x[b, ci, (l+k) mod L] * W[co, ci, k]
//
// R13 (warp-autonomous one-shot, best: 47.1us) with ONE structural change:
// positions per thread halved (4 instead of 8) -> acc 64->32 regs,
// xw 16->8 regs, so the register footprint drops from 117 to ~90 and
// occupancy rises from 4 to 5 blocks/SM (20 warps). DRAM traffic unchanged
// (tiles are SMEM-staged per warp; only the 16B/ci halo duplicates).
// Each warp owns 128 positions + private weight copy; sync = __syncwarp only.
// Lane owns positions [4*lid, 4*lid+4): conflict-free LDS.128 windows,
// warp-coalesced STG.128 stores. All 8 co as 4 f32x2-packed pairs.
// ----------------------------------------------------------------------------
__global__ __launch_bounds__(TPB, 5)
void conv_pbc_kernel(const float* __restrict__ x,
                     const float* __restrict__ W,
                     const float* __restrict__ bias,
                     float* __restrict__ out)
{
    __shared__ float xs[4][CIN][ROWW];                        // per-warp x
    __shared__ __align__(16) float2 w2s[4][CIN][FS][COUT / 2];// per-warp W
    __shared__ float2 b2s[4][COUT / 2];                       // per-warp bias

    const int t   = threadIdx.x;
    const int w   = t >> 5;
    const int lid = t & 31;

    const int b    = blockIdx.x >> 7;                        // 128 chunks/batch
    const int base = ((blockIdx.x & 127) << 9) + (w << 7);   // warp's 128 pos

    const float* __restrict__ xb = x + (size_t)b * CIN * L_LEN;

    // ---- stage x: 8 coalesced LDG.128 + halo, all issued before any STS ----
    float4 va[CIN], vh;
    #pragma unroll
    for (int ci = 0; ci < CIN; ++ci)
        va[ci] = reinterpret_cast<const float4*>(
                     xb + (size_t)ci * L_LEN + base)[lid];
    if (lid < CIN)   // halo: 4 floats past the warp region, circular, aligned
        vh = *reinterpret_cast<const float4*>(
            xb + (size_t)lid * L_LEN + ((base + WTILE) & L_MASK));

    #pragma unroll
    for (int ci = 0; ci < CIN; ++ci)
        *reinterpret_cast<float4*>(&xs[w][ci][4 * lid]) = va[ci];
    if (lid < CIN)
        *reinterpret_cast<float4*>(&xs[w][lid][WTILE]) = vh;

    // ---- per-warp weights/bias (after x STS to keep the register peak) ----
    {
        const int ci = (lid >> 2) & 7;
        const int k  = lid & 3;
        #pragma unroll
        for (int cp = 0; cp < 4; ++cp)
            w2s[w][ci][k][cp] =
                make_float2(W[(2 * cp)     * CIN * FS + ci * FS + k],
                            W[(2 * cp + 1) * CIN * FS + ci * FS + k]);
        if (lid < COUT / 2)
            b2s[w][lid] = make_float2(bias[2 * lid], bias[2 * lid + 1]);
    }
    __syncwarp();                                // the ONLY sync in the kernel

    // ---- accumulators: acc[q][cp], init = bias ----
    float2 acc[4][COUT / 2];
    {
        const float2 c0 = b2s[w][0], c1 = b2s[w][1],
                     c2 = b2s[w][2], c3 = b2s[w][3];
        #pragma unroll
        for (int q = 0; q < 4; ++q) {
            acc[q][0] = c0; acc[q][1] = c1; acc[q][2] = c2; acc[q][3] = c3;
        }
    }

    // ---- monolithic compute from SMEM ----
    #pragma unroll
    for (int ci = 0; ci < CIN; ++ci) {
        // packed weights for this ci: 2 broadcast LDS.128 per k
        float2 wv[FS][COUT / 2];
        #pragma unroll
        for (int k = 0; k < FS; ++k) {
            const float4 wa = *reinterpret_cast<const float4*>(&w2s[w][ci][k][0]);
            const float4 wb = *reinterpret_cast<const float4*>(&w2s[w][ci][k][2]);
            wv[k][0] = make_float2(wa.x, wa.y);
            wv[k][1] = make_float2(wa.z, wa.w);
            wv[k][2] = make_float2(wb.x, wb.y);
            wv[k][3] = make_float2(wb.z, wb.w);
        }

        // 7-float window: two conflict-free LDS.128
        float xw[8];
        {
            const float4 a0 = *reinterpret_cast<const float4*>(&xs[w][ci][4 * lid]);
            const float4 a1 = *reinterpret_cast<const float4*>(&xs[w][ci][4 * lid + 4]);
            xw[0] = a0.x; xw[1] = a0.y; xw[2] = a0.z; xw[3] = a0.w;
            xw[4] = a1.x; xw[5] = a1.y; xw[6] = a1.z; xw[7] = a1.w;
        }

        #pragma unroll
        for (int i = 0; i < 7; ++i) {
            const float2 xk = dup2(xw[i]);
            #pragma unroll
            for (int k = 0; k < FS; ++k) {
                const int q = i - k;
                if (q >= 0 && q < 4) {
                    #pragma unroll
                    for (int cp = 0; cp < 4; ++cp)
                        acc[q][cp] = ffma2(wv[k][cp], xk, acc[q][cp]);
                }
            }
        }
    }

    // ---- epilogue: warp-coalesced STG.128 per co ----
    float* __restrict__ ob = out + (size_t)b * COUT * L_LEN + base + 4 * lid;
    #pragma unroll
    for (int cp = 0; cp < 4; ++cp) {
        float4 v;
        v.x = acc[0][cp].x; v.y = acc[1][cp].x;
        v.z = acc[2][cp].x; v.w = acc[3][cp].x;
        *reinterpret_cast<float4*>(ob + (size_t)(2 * cp) * L_LEN) = v;
        v.x = acc[0][cp].y; v.y = acc[1][cp].y;
        v.z = acc[2][cp].y; v.w = acc[3][cp].y;
        *reinterpret_cast<float4*>(ob + (size_t)(2 * cp + 1) * L_LEN) = v;
    }
}

extern "C" void kernel_launch(void* const* d_in, const int* in_sizes, int n_in,
                              void* d_out, int out_size)
{
    const float* x    = (const float*)d_in[0];  // (64, 8, 65536)
    const float* W    = (const float*)d_in[1];  // (8, 8, 4)
    const float* bias = (const float*)d_in[2];  // (8,)
    float* out        = (float*)d_out;          // (64, 8, 65536)

    // 64 batches * 128 chunks (512 positions, 128 per warp) = 8192 blocks
    conv_pbc_kernel<<<64 * (L_LEN / 512), TPB>>>(x, W, bias, out);
}

// round 17
// speedup vs baseline: 1.0700x; 1.0025x over previous
#include <cuda_runtime.h>
#include <cstdint>

#define L_LEN   65536
#define L_MASK  (L_LEN - 1)
#define CIN     8
#define COUT    8
#define FS      4
#define TPB     128        // 4 autonomous warps per block
#define WTILE   128        // positions per warp
#define ROWW    132        // 128 + 4 halo floats, 16B-aligned row stride

// ---- packed f32x2 helpers (Blackwell sm_100a+) ------------------------------
__device__ __forceinline__ float2 ffma2(float2 a, float2 b, float2 c) {
    float2 d;
    asm("fma.rn.f32x2 %0, %1, %2, %3;"
        : "=l"(reinterpret_cast<unsigned long long&>(d))
        : "l"(reinterpret_cast<const unsigned long long&>(a)),
          "l"(reinterpret_cast<const unsigned long long&>(b)),
          "l"(reinterpret_cast<const unsigned long long&>(c)));
    return d;
}

__device__ __forceinline__ float2 dup2(float x) {
    float2 d;
    asm("mov.b64 %0, {%1, %1};"
        : "=l"(reinterpret_cast<unsigned long long&>(d))
        : "f"(x));
    return d;
}

// ----------------------------------------------------------------------------
// out[b, co, l] = bias[co] + sum_{ci,k} x[b, ci, (l+k) mod L] * W[co, ci, k]
//
// R13 (warp-autonomous one-shot, best: 47.1us) with ONE structural change:
// positions per thread halved (4 instead of 8) -> acc 64->32 regs,
// xw 16->8 regs, so the register footprint drops from 117 to ~90 and
// occupancy rises from 4 to 5 blocks/SM (20 warps). DRAM traffic unchanged
// (tiles are SMEM-staged per warp; only the 16B/ci halo duplicates).
// Each warp owns 128 positions + private weight copy; sync = __syncwarp only.
// Lane owns positions [4*lid, 4*lid+4): conflict-free LDS.128 windows,
// warp-coalesced STG.128 stores. All 8 co as 4 f32x2-packed pairs.
// ----------------------------------------------------------------------------
__global__ __launch_bounds__(TPB, 5)
void conv_pbc_kernel(const float* __restrict__ x,
                     const float* __restrict__ W,
                     const float* __restrict__ bias,
                     float* __restrict__ out)
{
    __shared__ float xs[4][CIN][ROWW];                        // per-warp x
    __shared__ __align__(16) float2 w2s[4][CIN][FS][COUT / 2];// per-warp W
    __shared__ float2 b2s[4][COUT / 2];                       // per-warp bias

    const int t   = threadIdx.x;
    const int w   = t >> 5;
    const int lid = t & 31;

    const int b    = blockIdx.x >> 7;                        // 128 chunks/batch
    const int base = ((blockIdx.x & 127) << 9) + (w << 7);   // warp's 128 pos

    const float* __restrict__ xb = x + (size_t)b * CIN * L_LEN;

    // ---- stage x: 8 coalesced LDG.128 + halo, all issued before any STS ----
    float4 va[CIN], vh;
    #pragma unroll
    for (int ci = 0; ci < CIN; ++ci)
        va[ci] = reinterpret_cast<const float4*>(
                     xb + (size_t)ci * L_LEN + base)[lid];
    if (lid < CIN)   // halo: 4 floats past the warp region, circular, aligned
        vh = *reinterpret_cast<const float4*>(
            xb + (size_t)lid * L_LEN + ((base + WTILE) & L_MASK));

    #pragma unroll
    for (int ci = 0; ci < CIN; ++ci)
        *reinterpret_cast<float4*>(&xs[w][ci][4 * lid]) = va[ci];
    if (lid < CIN)
        *reinterpret_cast<float4*>(&xs[w][lid][WTILE]) = vh;

    // ---- per-warp weights/bias (after x STS to keep the register peak) ----
    {
        const int ci = (lid >> 2) & 7;
        const int k  = lid & 3;
        #pragma unroll
        for (int cp = 0; cp < 4; ++cp)
            w2s[w][ci][k][cp] =
                make_float2(W[(2 * cp)     * CIN * FS + ci * FS + k],
                            W[(2 * cp + 1) * CIN * FS + ci * FS + k]);
        if (lid < COUT / 2)
            b2s[w][lid] = make_float2(bias[2 * lid], bias[2 * lid + 1]);
    }
    __syncwarp();                                // the ONLY sync in the kernel

    // ---- accumulators: acc[q][cp], init = bias ----
    float2 acc[4][COUT / 2];
    {
        const float2 c0 = b2s[w][0], c1 = b2s[w][1],
                     c2 = b2s[w][2], c3 = b2s[w][3];
        #pragma unroll
        for (int q = 0; q < 4; ++q) {
            acc[q][0] = c0; acc[q][1] = c1; acc[q][2] = c2; acc[q][3] = c3;
        }
    }

    // ---- monolithic compute from SMEM ----
    #pragma unroll
    for (int ci = 0; ci < CIN; ++ci) {
        // packed weights for this ci: 2 broadcast LDS.128 per k
        float2 wv[FS][COUT / 2];
        #pragma unroll
        for (int k = 0; k < FS; ++k) {
            const float4 wa = *reinterpret_cast<const float4*>(&w2s[w][ci][k][0]);
            const float4 wb = *reinterpret_cast<const float4*>(&w2s[w][ci][k][2]);
            wv[k][0] = make_float2(wa.x, wa.y);
            wv[k][1] = make_float2(wa.z, wa.w);
            wv[k][2] = make_float2(wb.x, wb.y);
            wv[k][3] = make_float2(wb.z, wb.w);
        }

        // 7-float window: two conflict-free LDS.128
        float xw[8];
        {
            const float4 a0 = *reinterpret_cast<const float4*>(&xs[w][ci][4 * lid]);
            const float4 a1 = *reinterpret_cast<const float4*>(&xs[w][ci][4 * lid + 4]);
            xw[0] = a0.x; xw[1] = a0.y; xw[2] = a0.z; xw[3] = a0.w;
            xw[4] = a1.x; xw[5] = a1.y; xw[6] = a1.z; xw[7] = a1.w;
        }

        #pragma unroll
        for (int i = 0; i < 7; ++i) {
            const float2 xk = dup2(xw[i]);
            #pragma unroll
            for (int k = 0; k < FS; ++k) {
                const int q = i - k;
                if (q >= 0 && q < 4) {
                    #pragma unroll
                    for (int cp = 0; cp < 4; ++cp)
                        acc[q][cp] = ffma2(wv[k][cp], xk, acc[q][cp]);
                }
            }
        }
    }

    // ---- epilogue: warp-coalesced STG.128 per co ----
    float* __restrict__ ob = out + (size_t)b * COUT * L_LEN + base + 4 * lid;
    #pragma unroll
    for (int cp = 0; cp < 4; ++cp) {
        float4 v;
        v.x = acc[0][cp].x; v.y = acc[1][cp].x;
        v.z = acc[2][cp].x; v.w = acc[3][cp].x;
        *reinterpret_cast<float4*>(ob + (size_t)(2 * cp) * L_LEN) = v;
        v.x = acc[0][cp].y; v.y = acc[1][cp].y;
        v.z = acc[2][cp].y; v.w = acc[3][cp].y;
        *reinterpret_cast<float4*>(ob + (size_t)(2 * cp + 1) * L_LEN) = v;
    }
}

extern "C" void kernel_launch(void* const* d_in, const int* in_sizes, int n_in,
                              void* d_out, int out_size)
{
    const float* x    = (const float*)d_in[0];  // (64, 8, 65536)
    const float* W    = (const float*)d_in[1];  // (8, 8, 4)
    const float* bias = (const float*)d_in[2];  // (8,)
    float* out        = (float*)d_out;          // (64, 8, 65536)

    // 64 batches * 128 chunks (512 positions, 128 per warp) = 8192 blocks
    conv_pbc_kernel<<<64 * (L_LEN / 512), TPB>>>(x, W, bias, out);
}